// round 13
// baseline (speedup 1.0000x reference)
#include <cuda_runtime.h>
#include <cstdint>

#define Bdim 8
#define Ndim 512
#define Pdim 16
#define Cdim 512
#define HD   64
#define BN   (Bdim*Ndim)
#define BNP  (BN*Pdim)
#define BH   (Bdim*8)
#define EP   (HD*Pdim)

#define OFF_XQ 0ull
#define OFF_XK (OFF_XQ + (size_t)BN*Cdim)
#define OFF_Q  (OFF_XK + (size_t)BN*Cdim)
#define OFF_K  (OFF_Q  + (size_t)BN*Cdim)
#define OFF_V  (OFF_K  + (size_t)BN*Cdim)
#define OFF_S  (OFF_V  + (size_t)BNP*Cdim)
#define OFF_O2 (OFF_S  + (size_t)BH*Ndim*Ndim)
#define OFF_XC (OFF_O2 + (size_t)BNP*Cdim)
#define OFF_WC (OFF_XC + (size_t)BNP*Cdim)
#define OFF_WP (OFF_WC + (size_t)Cdim*3*Cdim)
#define SCRATCH_FLOATS (OFF_WP + (size_t)Cdim*Cdim)

__device__ float g_scratch[SCRATCH_FLOATS];

__device__ __forceinline__ uint32_t f2tf(float f) {
    uint32_t u;
    asm("cvt.rna.tf32.f32 %0, %1;" : "=r"(u) : "f"(f));
    return u;
}
__device__ __forceinline__ float f2tff(float f) { return __uint_as_float(f2tf(f)); }

__device__ __forceinline__ void cp16(uint32_t dst, const void* src) {
    asm volatile("cp.async.ca.shared.global [%0], [%1], 16;" :: "r"(dst), "l"(src));
}
__device__ __forceinline__ void cp_commit() {
    asm volatile("cp.async.commit_group;");
}
__device__ __forceinline__ void cp_wait1() {
    asm volatile("cp.async.wait_group 1;");
}

// dynamic smem (uint32 words), 3 stages:
//   As stage s: [s*4608 .. +4608)          (128 rows x 36)
//   Bs stage s: [13824 + s*4352 ..)        (32 rows x 136)
#define ASTG 4608
#define BBASE (3*ASTG)
#define BSTG 4352
#define SMEM_WORDS (BBASE + 3*BSTG)   /* 26880 words = 107520 B */

// ---------------- prep: xq/xk (tf32-rounded) + converted copy of x ---------
__global__ void prep_kernel(const float* __restrict__ x,
                            const float* __restrict__ mask,
                            float* __restrict__ xq, float* __restrict__ xk,
                            float* __restrict__ xc) {
    int bn = blockIdx.x, c = threadIdx.x;
    const float* xb = x + (size_t)bn * Pdim * Cdim;
    float* xcb = xc + (size_t)bn * Pdim * Cdim;
    const float* mb = mask + (size_t)bn * Pdim;
    float cnt = 0.f, s = 0.f;
#pragma unroll
    for (int p = 0; p < Pdim; p++) {
        float m = mb[p];
        float v = xb[(size_t)p * Cdim + c];
        cnt += m;
        s += m * v;
        xcb[(size_t)p * Cdim + c] = f2tff(v);
    }
    xq[(size_t)bn * Cdim + c] = f2tff(xb[c]);
    xk[(size_t)bn * Cdim + c] = f2tff(s / cnt);
}

// ---------------- elementwise tf32 convert copy ----------------------------
__global__ void cvt_copy_kernel(const float* __restrict__ src,
                                float* __restrict__ dst, int n) {
    int i = blockIdx.x * 256 + threadIdx.x;
    if (i < n) dst[i] = f2tff(src[i]);
}

// ---------------- tf32 tensor GEMM, 3-stage cp.async + ldmatrix A ----------
// 128x128 tile, BK=32, 256 threads (8 warps, 2x4 grid, 64x32 warp tile).
// All operands must be PRE-ROUNDED to tf32 (cvt at producers).
// AM: 0 = A row-major [M,K];       1 = gather A from O2[bh][n][p*64+d]
// BM: 0 = B row-major [K,N];       1 = gather B[k=m][n=p*64+d] from V
//     2 = B[k][n] = Bm[n*ldb + k]  (transposed; legacy LDG+cvt staging)
template<int AM, int BM>
__global__ void __launch_bounds__(256, 2)
tgemm_kernel(const float* __restrict__ A, int lda, size_t sAb, size_t sAh,
             const float* __restrict__ Bm, int ldb, size_t sBb, size_t sBh,
             float* __restrict__ Cm, int ldc, size_t sCb, size_t sCh,
             int K, float alpha, const float* __restrict__ bias, int cvt_out) {
    extern __shared__ uint32_t smw[];
    const uint32_t sbase = (uint32_t)__cvta_generic_to_shared(smw);
    const int zb = blockIdx.z >> 3, zh = blockIdx.z & 7;
    A  += (size_t)zb * sAb + (size_t)zh * sAh;
    Bm += (size_t)zb * sBb + (size_t)zh * sBh;
    Cm += (size_t)zb * sCb + (size_t)zh * sCh;

    const int tid  = threadIdx.x;
    const int lane = tid & 31, warp = tid >> 5;
    const int g    = lane >> 2, tig = lane & 3;
    const int wm   = (warp >> 2) * 64;
    const int wn   = (warp & 3) * 32;
    const size_t row0 = (size_t)blockIdx.y * 128;
    const int col0 = blockIdx.x * 128;

    float acc[4][4][4];
#pragma unroll
    for (int mi = 0; mi < 4; mi++)
#pragma unroll
        for (int ni = 0; ni < 4; ni++)
#pragma unroll
            for (int r = 0; r < 4; r++) acc[mi][ni][r] = 0.f;

    const int ar = tid >> 3;        // 0..31 (+32*i)
    const int ac = (tid & 7) * 4;   // 0..28 within BK
    const int br = tid >> 3;        // k-row 0..31
    const int bc = (tid & 7) * 4;   // 0..28 (+32*i)
    const int tn = tid & 127, tkh = tid >> 7;   // BT staging

    // ldmatrix lane source: row = wm + 16*mi + a_lm_row; k-word = ks*8 + a_lm_k
    const int a_lm_row = (lane & 7) + 8 * ((lane >> 3) & 1);
    const int a_lm_k   = 4 * (lane >> 4);

    size_t gaBase[4];
    if (AM == 1) {
#pragma unroll
        for (int i = 0; i < 4; i++) {
            size_t row = row0 + ar + 32 * i;
            int ab = (int)(row >> 13);
            int an = (int)(row >> 4) & 511;
            int ap = (int)row & 15;
            gaBase[i] = (((size_t)ab * 8) * 512 + an) * 1024 + (size_t)ap * 64;
        }
    }

    auto copyA = [&](int st, int k0) {
        uint32_t d0 = sbase + (st * ASTG) * 4;
#pragma unroll
        for (int i = 0; i < 4; i++) {
            uint32_t dst = d0 + ((ar + 32 * i) * 36 + ac) * 4;
            const float* src;
            if (AM == 0) {
                src = A + (row0 + ar + 32 * i) * lda + k0 + ac;
            } else {
                int k = k0 + ac;
                int h = k >> 6, d = k & 63;
                src = A + gaBase[i] + (size_t)h * (512 * 1024) + d;
            }
            cp16(dst, src);
        }
    };
    auto copyB = [&](int st, int k0) {
        uint32_t d0 = sbase + (BBASE + st * BSTG) * 4;
        if (BM == 0) {
#pragma unroll
            for (int i = 0; i < 4; i++)
                cp16(d0 + (br * 136 + bc + 32 * i) * 4,
                     Bm + (size_t)(k0 + br) * ldb + col0 + bc + 32 * i);
        } else if (BM == 1) {
#pragma unroll
            for (int i = 0; i < 4; i++) {
                int n = col0 + bc + 32 * i;
                int pp = n >> 6, dd = n & 63;
                cp16(d0 + (br * 136 + bc + 32 * i) * 4,
                     Bm + ((size_t)(k0 + br) * 16 + pp) * 512 + dd);
            }
        } else {
            uint32_t* Bs = smw + BBASE + st * BSTG;
            const float* bcol = Bm + (size_t)(col0 + tn) * ldb + k0 + 16 * tkh;
#pragma unroll
            for (int i = 0; i < 4; i++) {
                float4 v = *(const float4*)(bcol + 4 * i);
                int k = 16 * tkh + 4 * i;
                Bs[(k + 0) * 136 + tn] = f2tf(v.x);
                Bs[(k + 1) * 136 + tn] = f2tf(v.y);
                Bs[(k + 2) * 136 + tn] = f2tf(v.z);
                Bs[(k + 3) * 136 + tn] = f2tf(v.w);
            }
        }
    };

    const int K32 = K >> 5;
    // prologue: stages 0 and 1 (always one commit each; K32 >= 2 for all uses)
    copyA(0, 0); copyB(0, 0);
    cp_commit();
    if (K32 > 1) { copyA(1, 32); copyB(1, 32); }
    cp_commit();

    for (int it = 0; it < K32; it++) {
        const int st = it % 3;
        cp_wait1();            // stage `it` complete; stage `it+1` may be in flight
        __syncthreads();

        if (it + 2 < K32) {
            const int sn = (it + 2) % 3;
            copyA(sn, (it + 2) * 32);
            copyB(sn, (it + 2) * 32);
        }
        cp_commit();           // exactly one group per iteration (may be empty)

        const uint32_t aBase = sbase + (st * ASTG) * 4;
        const uint32_t* Bs = smw + BBASE + st * BSTG;
#pragma unroll
        for (int ks = 0; ks < 4; ks++) {
            const int k8 = ks * 8;
            uint32_t a[4][4], b[4][2];
#pragma unroll
            for (int mi = 0; mi < 4; mi++) {
                uint32_t addr = aBase +
                    ((wm + 16 * mi + a_lm_row) * 36 + k8 + a_lm_k) * 4;
                asm volatile(
                    "ldmatrix.sync.aligned.m8n8.x4.shared.b16 {%0,%1,%2,%3}, [%4];"
                    : "=r"(a[mi][0]), "=r"(a[mi][1]),
                      "=r"(a[mi][2]), "=r"(a[mi][3])
                    : "r"(addr));
            }
#pragma unroll
            for (int ni = 0; ni < 4; ni++) {
                int n = wn + ni * 8 + g;
                b[ni][0] = Bs[(k8 + tig) * 136 + n];
                b[ni][1] = Bs[(k8 + tig + 4) * 136 + n];
            }
#pragma unroll
            for (int mi = 0; mi < 4; mi++)
#pragma unroll
                for (int ni = 0; ni < 4; ni++) {
                    asm volatile(
                        "mma.sync.aligned.m16n8k8.row.col.f32.tf32.tf32.f32 "
                        "{%0,%1,%2,%3}, {%4,%5,%6,%7}, {%8,%9}, {%0,%1,%2,%3};"
                        : "+f"(acc[mi][ni][0]), "+f"(acc[mi][ni][1]),
                          "+f"(acc[mi][ni][2]), "+f"(acc[mi][ni][3])
                        : "r"(a[mi][0]), "r"(a[mi][1]), "r"(a[mi][2]), "r"(a[mi][3]),
                          "r"(b[ni][0]), "r"(b[ni][1]));
                }
        }
    }

#pragma unroll
    for (int mi = 0; mi < 4; mi++) {
        size_t r = row0 + wm + mi * 16 + g;
#pragma unroll
        for (int ni = 0; ni < 4; ni++) {
            int c = col0 + wn + ni * 8 + tig * 2;
            float bx = 0.f, by = 0.f;
            if (bias) { bx = bias[c]; by = bias[c + 1]; }
            float o0 = acc[mi][ni][0] * alpha + bx;
            float o1 = acc[mi][ni][1] * alpha + by;
            float o2 = acc[mi][ni][2] * alpha + bx;
            float o3 = acc[mi][ni][3] * alpha + by;
            if (cvt_out) {
                o0 = f2tff(o0); o1 = f2tff(o1); o2 = f2tff(o2); o3 = f2tff(o3);
            }
            *(float2*)&Cm[r * ldc + c] = make_float2(o0, o1);
            *(float2*)&Cm[(r + 8) * ldc + c] = make_float2(o2, o3);
        }
    }
}

// ---------------- softmax (rows of 512), tf32-rounded output ---------------
__global__ void __launch_bounds__(256)
softmax_kernel(float* __restrict__ S) {
    float* r = S + (size_t)blockIdx.x * Ndim;
    int tid = threadIdx.x;
    float v0 = r[tid], v1 = r[tid + 256];
    __shared__ float red[8];
    unsigned full = 0xffffffffu;
    float m = fmaxf(v0, v1);
#pragma unroll
    for (int o = 16; o; o >>= 1) m = fmaxf(m, __shfl_xor_sync(full, m, o));
    if ((tid & 31) == 0) red[tid >> 5] = m;
    __syncthreads();
    float mm = fmaxf(fmaxf(fmaxf(red[0], red[1]), fmaxf(red[2], red[3])),
                     fmaxf(fmaxf(red[4], red[5]), fmaxf(red[6], red[7])));
    __syncthreads();
    float e0 = __expf(v0 - mm), e1 = __expf(v1 - mm);
    float s = e0 + e1;
#pragma unroll
    for (int o = 16; o; o >>= 1) s += __shfl_xor_sync(full, s, o);
    if ((tid & 31) == 0) red[tid >> 5] = s;
    __syncthreads();
    float inv = 1.0f / (red[0]+red[1]+red[2]+red[3]+red[4]+red[5]+red[6]+red[7]);
    r[tid] = f2tff(e0 * inv);
    r[tid + 256] = f2tff(e1 * inv);
}

// ---------------------------------------------------------------------------
extern "C" void kernel_launch(void* const* d_in, const int* in_sizes, int n_in,
                              void* d_out, int out_size) {
    const float* x     = (const float*)d_in[0];
    const float* mask  = (const float*)d_in[1];
    const float* Wqkv  = (const float*)d_in[4];
    const float* Wproj = (const float*)d_in[5];
    const float* bproj = (const float*)d_in[6];
    float* out = (float*)d_out;

    float* sc = nullptr;
    cudaGetSymbolAddress((void**)&sc, g_scratch);
    float* xq = sc + OFF_XQ;
    float* xk = sc + OFF_XK;
    float* Qb = sc + OFF_Q;
    float* Kb = sc + OFF_K;
    float* Vb = sc + OFF_V;
    float* Sb = sc + OFF_S;
    float* O2 = sc + OFF_O2;
    float* xc = sc + OFF_XC;
    float* Wc = sc + OFF_WC;
    float* Wp = sc + OFF_WP;

    const size_t sNC = (size_t)BN * Cdim;           // 2097152
    const size_t sNN = (size_t)Ndim * Ndim;         // 262144
    const size_t sNE = (size_t)Ndim * EP;           // 524288
    const size_t sVB = (size_t)Ndim * Pdim * Cdim;  // 4194304
    const int SMB = SMEM_WORDS * 4;                 // 107520 B

    cudaFuncSetAttribute(tgemm_kernel<0,0>, cudaFuncAttributeMaxDynamicSharedMemorySize, SMB);
    cudaFuncSetAttribute(tgemm_kernel<0,1>, cudaFuncAttributeMaxDynamicSharedMemorySize, SMB);
    cudaFuncSetAttribute(tgemm_kernel<0,2>, cudaFuncAttributeMaxDynamicSharedMemorySize, SMB);
    cudaFuncSetAttribute(tgemm_kernel<1,0>, cudaFuncAttributeMaxDynamicSharedMemorySize, SMB);

    // 0. tf32-convert weights
    cvt_copy_kernel<<<(Cdim * 3 * Cdim + 255) / 256, 256>>>(Wqkv, Wc, Cdim * 3 * Cdim);
    cvt_copy_kernel<<<(Cdim * Cdim + 255) / 256, 256>>>(Wproj, Wp, Cdim * Cdim);

    // 1. prep: xq/xk (converted) + converted x copy
    prep_kernel<<<BN, Cdim>>>(x, mask, xq, xk, xc);

    // 2. Q and K fused (z=0: xq@Wq -> Qb, z=1: xk@Wk -> Kb); outputs tf32
    tgemm_kernel<0,0><<<dim3(4, 32, 2), 256, SMB>>>(
        xq, Cdim, 0, sNC, Wc, 3 * Cdim, 0, 512, Qb, Cdim, 0, sNC,
        Cdim, 1.f, nullptr, 1);

    // 3. V = xc @ Wv; output tf32
    tgemm_kernel<0,0><<<dim3(4, BNP / 128, 1), 256, SMB>>>(
        xc, Cdim, 0, 0, Wc + 2 * Cdim, 3 * Cdim, 0, 0, Vb, Cdim, 0, 0,
        Cdim, 1.f, nullptr, 1);

    // 4. scores: S = 0.125 * Q @ K^T  (BT mode, K=64, per bh); fp32 out
    tgemm_kernel<0,2><<<dim3(4, 4, BH), 256, SMB>>>(
        Qb, Cdim, (size_t)Ndim * Cdim, HD,
        Kb, Cdim, (size_t)Ndim * Cdim, HD,
        Sb, Ndim, 8 * sNN, sNN,
        HD, 0.125f, nullptr, 0);

    // 5. softmax (tf32-rounded output)
    softmax_kernel<<<BH * Ndim, 256>>>(Sb);

    // 6. O2[bh][n][p*64+d] = S @ Vgather  (K=512, N=1024, per bh); tf32 out
    tgemm_kernel<0,1><<<dim3(8, 4, BH), 256, SMB>>>(
        Sb, Ndim, 8 * sNN, sNN,
        Vb, 0, sVB, (size_t)HD,
        O2, EP, 8 * sNE, sNE,
        Ndim, 1.f, nullptr, 1);

    // 7. proj: out = Ogather @ Wp + bproj; fp32 out
    tgemm_kernel<1,0><<<dim3(4, BNP / 128, 1), 256, SMB>>>(
        O2, 0, 0, 0, Wp, Cdim, 0, 0, out, Cdim, 0, 0,
        Cdim, 1.f, bproj, 0);
}

// round 15
// speedup vs baseline: 1.1940x; 1.1940x over previous
#include <cuda_runtime.h>
#include <cstdint>

#define Bdim 8
#define Ndim 512
#define Pdim 16
#define Cdim 512
#define HD   64
#define BN   (Bdim*Ndim)
#define BNP  (BN*Pdim)
#define BH   (Bdim*8)
#define EP   (HD*Pdim)

#define OFF_XQ 0ull
#define OFF_XK (OFF_XQ + (size_t)BN*Cdim)
#define OFF_Q  (OFF_XK + (size_t)BN*Cdim)
#define OFF_K  (OFF_Q  + (size_t)BN*Cdim)
#define OFF_V  (OFF_K  + (size_t)BN*Cdim)
#define OFF_S  (OFF_V  + (size_t)BNP*Cdim)
#define OFF_O2 (OFF_S  + (size_t)BH*Ndim*Ndim)
#define OFF_WC (OFF_O2 + (size_t)BNP*Cdim)
#define OFF_WP (OFF_WC + (size_t)Cdim*3*Cdim)
#define SCRATCH_FLOATS (OFF_WP + (size_t)Cdim*Cdim)

__device__ float g_scratch[SCRATCH_FLOATS];

__device__ __forceinline__ uint32_t f2tf(float f) {
    uint32_t u;
    asm("cvt.rna.tf32.f32 %0, %1;" : "=r"(u) : "f"(f));
    return u;
}
__device__ __forceinline__ float f2tff(float f) { return __uint_as_float(f2tf(f)); }

__device__ __forceinline__ void cp16(uint32_t dst, const void* src) {
    asm volatile("cp.async.ca.shared.global [%0], [%1], 16;" :: "r"(dst), "l"(src));
}
__device__ __forceinline__ void cp_commit() {
    asm volatile("cp.async.commit_group;");
}
__device__ __forceinline__ void cp_wait0() {
    asm volatile("cp.async.wait_group 0;");
}

// dynamic smem (uint32 words), 2 stages:
//   As stage s: [s*4608 .. +4608)        (128 rows x 36)
//   Bs stage s: [9216 + s*4352 ..)       (32 rows x 136)
#define ASTG 4608
#define BBASE (2*ASTG)
#define BSTG 4352
#define SMEM_WORDS (BBASE + 2*BSTG)   /* 17920 words = 71680 B */

// ---------------- prep: xq/xk (tf32-rounded) -------------------------------
__global__ void prep_kernel(const float* __restrict__ x,
                            const float* __restrict__ mask,
                            float* __restrict__ xq, float* __restrict__ xk) {
    int bn = blockIdx.x, c = threadIdx.x;
    const float* xb = x + (size_t)bn * Pdim * Cdim;
    const float* mb = mask + (size_t)bn * Pdim;
    float cnt = 0.f, s = 0.f;
#pragma unroll
    for (int p = 0; p < Pdim; p++) {
        float m = mb[p];
        cnt += m;
        s += m * xb[(size_t)p * Cdim + c];
    }
    xq[(size_t)bn * Cdim + c] = f2tff(xb[c]);
    xk[(size_t)bn * Cdim + c] = f2tff(s / cnt);
}

// ---------------- elementwise tf32 convert copy ----------------------------
__global__ void cvt_copy_kernel(const float* __restrict__ src,
                                float* __restrict__ dst, int n) {
    int i = blockIdx.x * 256 + threadIdx.x;
    if (i < n) dst[i] = f2tff(src[i]);
}

// ---------------- tf32 tensor GEMM, 2-stage cp.async + ldmatrix A ----------
// 128x128 tile, BK=32, 256 threads (8 warps, 2x4 grid, 64x32 warp tile).
// AM: 0 = A row-major, cp.async (pre-rounded tf32)
//     1 = gather A from O2[bh][n][p*64+d], cp.async (pre-rounded)
//     2 = A row-major RAW fp32: LDG-prefetch + cvt.rna + STS (rounds in-kernel)
// BM: 0 = B row-major [K,N], cp.async (pre-rounded)
//     1 = gather B[k=m][n=p*64+d] from V, cp.async (pre-rounded)
//     2 = B[k][n] = Bm[n*ldb + k]  (transposed; legacy LDG+cvt staging)
template<int AM, int BM>
__global__ void __launch_bounds__(256, 2)
tgemm_kernel(const float* __restrict__ A, int lda, size_t sAb, size_t sAh,
             const float* __restrict__ Bm, int ldb, size_t sBb, size_t sBh,
             float* __restrict__ Cm, int ldc, size_t sCb, size_t sCh,
             int K, float alpha, const float* __restrict__ bias, int cvt_out) {
    extern __shared__ uint32_t smw[];
    const uint32_t sbase = (uint32_t)__cvta_generic_to_shared(smw);
    const int zb = blockIdx.z >> 3, zh = blockIdx.z & 7;
    A  += (size_t)zb * sAb + (size_t)zh * sAh;
    Bm += (size_t)zb * sBb + (size_t)zh * sBh;
    Cm += (size_t)zb * sCb + (size_t)zh * sCh;

    const int tid  = threadIdx.x;
    const int lane = tid & 31, warp = tid >> 5;
    const int g    = lane >> 2, tig = lane & 3;
    const int wm   = (warp >> 2) * 64;
    const int wn   = (warp & 3) * 32;
    const size_t row0 = (size_t)blockIdx.y * 128;
    const int col0 = blockIdx.x * 128;

    float acc[4][4][4];
#pragma unroll
    for (int mi = 0; mi < 4; mi++)
#pragma unroll
        for (int ni = 0; ni < 4; ni++)
#pragma unroll
            for (int r = 0; r < 4; r++) acc[mi][ni][r] = 0.f;

    const int ar = tid >> 3;        // 0..31 (+32*i)
    const int ac = (tid & 7) * 4;   // 0..28 within BK
    const int br = tid >> 3;        // k-row 0..31
    const int bc = (tid & 7) * 4;   // 0..28 (+32*i)
    const int tn = tid & 127, tkh = tid >> 7;   // BT staging

    // ldmatrix lane source: row = wm + 16*mi + a_lm_row; k-word = ks*8 + a_lm_k
    const int a_lm_row = (lane & 7) + 8 * ((lane >> 3) & 1);
    const int a_lm_k   = 4 * (lane >> 4);

    size_t gaBase[4];
    if (AM == 1) {
#pragma unroll
        for (int i = 0; i < 4; i++) {
            size_t row = row0 + ar + 32 * i;
            int ab = (int)(row >> 13);
            int an = (int)(row >> 4) & 511;
            int ap = (int)row & 15;
            gaBase[i] = (((size_t)ab * 8) * 512 + an) * 1024 + (size_t)ap * 64;
        }
    }

    float4 aR[4];   // AM==2 LDG prefetch registers (dead in other modes)

    auto copyA = [&](int st, int k0) {   // AM 0/1: cp.async
        uint32_t d0 = sbase + (st * ASTG) * 4;
#pragma unroll
        for (int i = 0; i < 4; i++) {
            uint32_t dst = d0 + ((ar + 32 * i) * 36 + ac) * 4;
            const float* src;
            if (AM == 0) {
                src = A + (row0 + ar + 32 * i) * lda + k0 + ac;
            } else {
                int k = k0 + ac;
                int h = k >> 6, d = k & 63;
                src = A + gaBase[i] + (size_t)h * (512 * 1024) + d;
            }
            cp16(dst, src);
        }
    };
    auto ldgA_regs = [&](int k0) {       // AM 2: raw fp32 -> regs
#pragma unroll
        for (int i = 0; i < 4; i++)
            aR[i] = *(const float4*)(A + (row0 + ar + 32 * i) * lda + k0 + ac);
    };
    auto stsA_regs = [&](int st) {       // AM 2: cvt.rna + STS
        uint32_t* As = smw + st * ASTG;
#pragma unroll
        for (int i = 0; i < 4; i++) {
            int r = ar + 32 * i;
            As[r * 36 + ac + 0] = f2tf(aR[i].x);
            As[r * 36 + ac + 1] = f2tf(aR[i].y);
            As[r * 36 + ac + 2] = f2tf(aR[i].z);
            As[r * 36 + ac + 3] = f2tf(aR[i].w);
        }
    };
    auto copyB = [&](int st, int k0) {
        uint32_t d0 = sbase + (BBASE + st * BSTG) * 4;
        if (BM == 0) {
#pragma unroll
            for (int i = 0; i < 4; i++)
                cp16(d0 + (br * 136 + bc + 32 * i) * 4,
                     Bm + (size_t)(k0 + br) * ldb + col0 + bc + 32 * i);
        } else if (BM == 1) {
#pragma unroll
            for (int i = 0; i < 4; i++) {
                int n = col0 + bc + 32 * i;
                int pp = n >> 6, dd = n & 63;
                cp16(d0 + (br * 136 + bc + 32 * i) * 4,
                     Bm + ((size_t)(k0 + br) * 16 + pp) * 512 + dd);
            }
        } else {
            uint32_t* Bs = smw + BBASE + st * BSTG;
            const float* bcol = Bm + (size_t)(col0 + tn) * ldb + k0 + 16 * tkh;
#pragma unroll
            for (int i = 0; i < 4; i++) {
                float4 v = *(const float4*)(bcol + 4 * i);
                int k = 16 * tkh + 4 * i;
                Bs[(k + 0) * 136 + tn] = f2tf(v.x);
                Bs[(k + 1) * 136 + tn] = f2tf(v.y);
                Bs[(k + 2) * 136 + tn] = f2tf(v.z);
                Bs[(k + 3) * 136 + tn] = f2tf(v.w);
            }
        }
    };

    const int K32 = K >> 5;
    // prologue: stage 0
    if (AM == 2) {
        ldgA_regs(0);
        copyB(0, 0);
        cp_commit();
        stsA_regs(0);
    } else {
        copyA(0, 0); copyB(0, 0);
        cp_commit();
    }

    for (int it = 0; it < K32; it++) {
        const int st = it & 1;
        cp_wait0();
        __syncthreads();     // stage st ready (cp.async + any STS from last iter)

        const bool more = (it + 1 < K32);
        if (more) {
            if (AM == 2) ldgA_regs((it + 1) * 32);
            else copyA(st ^ 1, (it + 1) * 32);
            copyB(st ^ 1, (it + 1) * 32);
        }
        cp_commit();

        const uint32_t aBase = sbase + (st * ASTG) * 4;
        const uint32_t* Bs = smw + BBASE + st * BSTG;

        // B-fragment double buffer: prefetch b(ks+1) during mma(ks)
        uint32_t bfa[4][2], bfb[4][2];
        auto loadBf = [&](int k8, uint32_t (*bf)[2]) {
#pragma unroll
            for (int ni = 0; ni < 4; ni++) {
                int n = wn + ni * 8 + g;
                bf[ni][0] = Bs[(k8 + tig) * 136 + n];
                bf[ni][1] = Bs[(k8 + tig + 4) * 136 + n];
            }
        };
        loadBf(0, bfa);
#pragma unroll
        for (int ks = 0; ks < 4; ks++) {
            const int k8 = ks * 8;
            uint32_t a[4][4];
#pragma unroll
            for (int mi = 0; mi < 4; mi++) {
                uint32_t addr = aBase +
                    ((wm + 16 * mi + a_lm_row) * 36 + k8 + a_lm_k) * 4;
                asm volatile(
                    "ldmatrix.sync.aligned.m8n8.x4.shared.b16 {%0,%1,%2,%3}, [%4];"
                    : "=r"(a[mi][0]), "=r"(a[mi][1]),
                      "=r"(a[mi][2]), "=r"(a[mi][3])
                    : "r"(addr));
            }
            uint32_t (*bc_)[2] = (ks & 1) ? bfb : bfa;
            uint32_t (*bn_)[2] = (ks & 1) ? bfa : bfb;
            if (ks < 3) loadBf((ks + 1) * 8, bn_);
#pragma unroll
            for (int mi = 0; mi < 4; mi++)
#pragma unroll
                for (int ni = 0; ni < 4; ni++) {
                    asm volatile(
                        "mma.sync.aligned.m16n8k8.row.col.f32.tf32.tf32.f32 "
                        "{%0,%1,%2,%3}, {%4,%5,%6,%7}, {%8,%9}, {%0,%1,%2,%3};"
                        : "+f"(acc[mi][ni][0]), "+f"(acc[mi][ni][1]),
                          "+f"(acc[mi][ni][2]), "+f"(acc[mi][ni][3])
                        : "r"(a[mi][0]), "r"(a[mi][1]), "r"(a[mi][2]), "r"(a[mi][3]),
                          "r"(bc_[ni][0]), "r"(bc_[ni][1]));
                }
        }
        if (AM == 2 && more) stsA_regs(st ^ 1);
    }

#pragma unroll
    for (int mi = 0; mi < 4; mi++) {
        size_t r = row0 + wm + mi * 16 + g;
#pragma unroll
        for (int ni = 0; ni < 4; ni++) {
            int c = col0 + wn + ni * 8 + tig * 2;
            float bx = 0.f, by = 0.f;
            if (bias) { bx = bias[c]; by = bias[c + 1]; }
            float o0 = acc[mi][ni][0] * alpha + bx;
            float o1 = acc[mi][ni][1] * alpha + by;
            float o2 = acc[mi][ni][2] * alpha + bx;
            float o3 = acc[mi][ni][3] * alpha + by;
            if (cvt_out) {
                o0 = f2tff(o0); o1 = f2tff(o1); o2 = f2tff(o2); o3 = f2tff(o3);
            }
            *(float2*)&Cm[r * ldc + c] = make_float2(o0, o1);
            *(float2*)&Cm[(r + 8) * ldc + c] = make_float2(o2, o3);
        }
    }
}

// ---------------- softmax (rows of 512), tf32-rounded output ---------------
__global__ void __launch_bounds__(256)
softmax_kernel(float* __restrict__ S) {
    float* r = S + (size_t)blockIdx.x * Ndim;
    int tid = threadIdx.x;
    float v0 = r[tid], v1 = r[tid + 256];
    __shared__ float red[8];
    unsigned full = 0xffffffffu;
    float m = fmaxf(v0, v1);
#pragma unroll
    for (int o = 16; o; o >>= 1) m = fmaxf(m, __shfl_xor_sync(full, m, o));
    if ((tid & 31) == 0) red[tid >> 5] = m;
    __syncthreads();
    float mm = fmaxf(fmaxf(fmaxf(red[0], red[1]), fmaxf(red[2], red[3])),
                     fmaxf(fmaxf(red[4], red[5]), fmaxf(red[6], red[7])));
    __syncthreads();
    float e0 = __expf(v0 - mm), e1 = __expf(v1 - mm);
    float s = e0 + e1;
#pragma unroll
    for (int o = 16; o; o >>= 1) s += __shfl_xor_sync(full, s, o);
    if ((tid & 31) == 0) red[tid >> 5] = s;
    __syncthreads();
    float inv = 1.0f / (red[0]+red[1]+red[2]+red[3]+red[4]+red[5]+red[6]+red[7]);
    r[tid] = f2tff(e0 * inv);
    r[tid + 256] = f2tff(e1 * inv);
}

// ---------------------------------------------------------------------------
extern "C" void kernel_launch(void* const* d_in, const int* in_sizes, int n_in,
                              void* d_out, int out_size) {
    const float* x     = (const float*)d_in[0];
    const float* mask  = (const float*)d_in[1];
    const float* Wqkv  = (const float*)d_in[4];
    const float* Wproj = (const float*)d_in[5];
    const float* bproj = (const float*)d_in[6];
    float* out = (float*)d_out;

    float* sc = nullptr;
    cudaGetSymbolAddress((void**)&sc, g_scratch);
    float* xq = sc + OFF_XQ;
    float* xk = sc + OFF_XK;
    float* Qb = sc + OFF_Q;
    float* Kb = sc + OFF_K;
    float* Vb = sc + OFF_V;
    float* Sb = sc + OFF_S;
    float* O2 = sc + OFF_O2;
    float* Wc = sc + OFF_WC;
    float* Wp = sc + OFF_WP;

    const size_t sNC = (size_t)BN * Cdim;           // 2097152
    const size_t sNN = (size_t)Ndim * Ndim;         // 262144
    const size_t sNE = (size_t)Ndim * EP;           // 524288
    const size_t sVB = (size_t)Ndim * Pdim * Cdim;  // 4194304
    const int SMB = SMEM_WORDS * 4;                 // 71680 B

    cudaFuncSetAttribute(tgemm_kernel<0,0>, cudaFuncAttributeMaxDynamicSharedMemorySize, SMB);
    cudaFuncSetAttribute(tgemm_kernel<2,0>, cudaFuncAttributeMaxDynamicSharedMemorySize, SMB);
    cudaFuncSetAttribute(tgemm_kernel<0,1>, cudaFuncAttributeMaxDynamicSharedMemorySize, SMB);
    cudaFuncSetAttribute(tgemm_kernel<0,2>, cudaFuncAttributeMaxDynamicSharedMemorySize, SMB);
    cudaFuncSetAttribute(tgemm_kernel<1,0>, cudaFuncAttributeMaxDynamicSharedMemorySize, SMB);

    // 0. tf32-convert weights
    cvt_copy_kernel<<<(Cdim * 3 * Cdim + 255) / 256, 256>>>(Wqkv, Wc, Cdim * 3 * Cdim);
    cvt_copy_kernel<<<(Cdim * Cdim + 255) / 256, 256>>>(Wproj, Wp, Cdim * Cdim);

    // 1. prep: xq/xk (tf32-rounded)
    prep_kernel<<<BN, Cdim>>>(x, mask, xq, xk);

    // 2. Q and K fused (z=0: xq@Wq -> Qb, z=1: xk@Wk -> Kb); outputs tf32
    tgemm_kernel<0,0><<<dim3(4, 32, 2), 256, SMB>>>(
        xq, Cdim, 0, sNC, Wc, 3 * Cdim, 0, 512, Qb, Cdim, 0, sNC,
        Cdim, 1.f, nullptr, 1);

    // 3. V = tf32(x) @ Wv; A staged in-kernel from raw x (AM=2); output tf32
    tgemm_kernel<2,0><<<dim3(4, BNP / 128, 1), 256, SMB>>>(
        x, Cdim, 0, 0, Wc + 2 * Cdim, 3 * Cdim, 0, 0, Vb, Cdim, 0, 0,
        Cdim, 1.f, nullptr, 1);

    // 4. scores: S = 0.125 * Q @ K^T  (BT mode, K=64, per bh); fp32 out
    tgemm_kernel<0,2><<<dim3(4, 4, BH), 256, SMB>>>(
        Qb, Cdim, (size_t)Ndim * Cdim, HD,
        Kb, Cdim, (size_t)Ndim * Cdim, HD,
        Sb, Ndim, 8 * sNN, sNN,
        HD, 0.125f, nullptr, 0);

    // 5. softmax (tf32-rounded output)
    softmax_kernel<<<BH * Ndim, 256>>>(Sb);

    // 6. O2[bh][n][p*64+d] = S @ Vgather  (K=512, N=1024, per bh); tf32 out
    tgemm_kernel<0,1><<<dim3(8, 4, BH), 256, SMB>>>(
        Sb, Ndim, 8 * sNN, sNN,
        Vb, 0, sVB, (size_t)HD,
        O2, EP, 8 * sNE, sNE,
        Ndim, 1.f, nullptr, 1);

    // 7. proj: out = Ogather @ Wp + bproj; fp32 out
    tgemm_kernel<1,0><<<dim3(4, BNP / 128, 1), 256, SMB>>>(
        O2, 0, 0, 0, Wp, Cdim, 0, 0, out, Cdim, 0, 0,
        Cdim, 1.f, bproj, 0);
}